// round 2
// baseline (speedup 1.0000x reference)
#include <cuda_runtime.h>
#include <math.h>

#define NB 512
#define SS 128
#define TT 128
#define EE 128
#define HH 1024
#define VV 128
#define G3 (3*HH)

// ---------------- device scratch (no allocation allowed) ----------------
__device__ float g_h[2][NB*HH];          // double-buffered hidden state
__device__ float g_Gsrc[VV*G3];          // token -> gi table (encoder)
__device__ float g_Gtrg[VV*G3];          // token -> gi table (decoder)
__device__ int   g_tok[NB];              // current decoder input tokens
__device__ float g_pred_part[8][NB*VV];  // split-K partials for pred GEMM

// ---------------- build gi lookup tables ----------------
// G[v][c] = (v==PAD? 0 : sum_e emb[v][e]*Wih[c][e]) + bih[c]
__global__ void build_tables(const float* __restrict__ emb_src,
                             const float* __restrict__ enc_Wih,
                             const float* __restrict__ enc_bih,
                             const float* __restrict__ emb_trg,
                             const float* __restrict__ dec_Wih,
                             const float* __restrict__ dec_bih)
{
    int idx = blockIdx.x * blockDim.x + threadIdx.x;   // 2*128*3072
    int which = idx / (VV*G3);
    int rem   = idx % (VV*G3);
    int v = rem / G3;
    int c = rem % G3;
    const float* emb = which ? emb_trg : emb_src;
    const float* W   = which ? dec_Wih : enc_Wih;
    const float* bi  = which ? dec_bih : enc_bih;
    float s = bi[c];
    if (v != 0) {  // PAD_IDX row of embedding is zeroed
        const float* e = emb + v*EE;
        const float* w = W + c*EE;
        #pragma unroll 8
        for (int k = 0; k < EE; k++) s += e[k]*w[k];
    }
    float* G = which ? g_Gtrg : g_Gsrc;
    G[v*G3 + c] = s;
}

// ---------------- init: h0 = 0, out[:,0,:] = 0, tok = trg[:,0] ----------------
__global__ void init_kernel(float* __restrict__ out, const int* __restrict__ trg)
{
    int i = blockIdx.x * blockDim.x + threadIdx.x;
    if (i < NB*HH) g_h[0][i] = 0.0f;
    if (i < NB*VV) {
        int b = i / VV, v = i % VV;
        out[b*(TT*VV) + v] = 0.0f;
    }
    if (i < NB) g_tok[i] = trg[i*TT];
}

// ---------------- fused GRU step: gh GEMM (3 gates) + gate math ----------------
#define BM 64
#define BN 64     // h-columns per block (per gate)
#define BK 16
#define TM 8
#define TN 2
// blockDim = (32, 8) = 256 threads; grid = (HH/BN=16, NB/BM=8)
// table_sel: 0 -> g_Gsrc (encoder), 1 -> g_Gtrg (decoder)
// ext_tok: device pointer to tokens (encoder: src+t, stride SS); nullptr -> g_tok
__global__ __launch_bounds__(256, 1)
void gru_step(int pin,
              const float* __restrict__ Whh, const float* __restrict__ bhh,
              int table_sel,
              const int* __restrict__ ext_tok, int tok_stride)
{
    const float* __restrict__ h_in = g_h[pin];
    float* __restrict__ h_out      = g_h[pin ^ 1];
    const float* __restrict__ G    = table_sel ? g_Gtrg : g_Gsrc;
    const int* __restrict__ tokp   = ext_tok ? ext_tok : g_tok;

    __shared__ float As[BK][BM+4];
    __shared__ float Bs[3][BK][BN+4];

    const int row0 = blockIdx.y * BM;
    const int col0 = blockIdx.x * BN;
    const int tx = threadIdx.x, ty = threadIdx.y;
    const int tid = ty*32 + tx;

    float acc[3][TM][TN];
    #pragma unroll
    for (int g = 0; g < 3; g++)
        #pragma unroll
        for (int i = 0; i < TM; i++)
            #pragma unroll
            for (int j = 0; j < TN; j++) acc[g][i][j] = 0.0f;

    const int ar = tid >> 2;          // A row 0..63
    const int ak = (tid & 3) << 2;    // A kvec*4

    for (int kt = 0; kt < HH; kt += BK) {
        // load A tile (h): 64 rows x 16 k, k-major in smem
        float4 av = *(const float4*)&h_in[(row0 + ar)*HH + kt + ak];
        As[ak+0][ar] = av.x; As[ak+1][ar] = av.y;
        As[ak+2][ar] = av.z; As[ak+3][ar] = av.w;
        // load B tiles (Whh rows for 3 gates): 3 x 64 cols x 16 k
        #pragma unroll
        for (int gl = 0; gl < 3; gl++) {
            int t3 = gl*256 + tid;
            int g  = t3 >> 8;
            int wi = t3 & 255;
            int bc = wi >> 2;             // col 0..63
            int bk = (wi & 3) << 2;       // kvec*4
            float4 bv = *(const float4*)&Whh[(g*HH + col0 + bc)*HH + kt + bk];
            Bs[g][bk+0][bc] = bv.x; Bs[g][bk+1][bc] = bv.y;
            Bs[g][bk+2][bc] = bv.z; Bs[g][bk+3][bc] = bv.w;
        }
        __syncthreads();

        #pragma unroll
        for (int kk = 0; kk < BK; kk++) {
            float4 a0 = *(const float4*)&As[kk][ty*TM];
            float4 a1 = *(const float4*)&As[kk][ty*TM + 4];
            float a[TM] = {a0.x, a0.y, a0.z, a0.w, a1.x, a1.y, a1.z, a1.w};
            float b[3][TN];
            #pragma unroll
            for (int g = 0; g < 3; g++) {
                float2 bb = *(const float2*)&Bs[g][kk][tx*TN];
                b[g][0] = bb.x; b[g][1] = bb.y;
            }
            #pragma unroll
            for (int g = 0; g < 3; g++)
                #pragma unroll
                for (int i = 0; i < TM; i++)
                    #pragma unroll
                    for (int j = 0; j < TN; j++)
                        acc[g][i][j] += a[i] * b[g][j];
        }
        __syncthreads();
    }

    // fused gate epilogue
    #pragma unroll
    for (int i = 0; i < TM; i++) {
        int row = row0 + ty*TM + i;
        int tk = tokp[row * tok_stride];
        const float* Grow = G + tk*G3;
        #pragma unroll
        for (int j = 0; j < TN; j++) {
            int col = col0 + tx*TN + j;
            float gr = acc[0][i][j] + bhh[col];
            float gz = acc[1][i][j] + bhh[HH + col];
            float gn = acc[2][i][j] + bhh[2*HH + col];
            float r = 1.0f / (1.0f + expf(-(Grow[col]        + gr)));
            float z = 1.0f / (1.0f + expf(-(Grow[HH + col]   + gz)));
            float n = tanhf(Grow[2*HH + col] + r * gn);
            float hp = h_in[row*HH + col];
            h_out[row*HH + col] = (1.0f - z)*n + z*hp;
        }
    }
}

// ---------------- decoder pred GEMM, split-K partials ----------------
// grid = (NB/32=16, KSPLIT=8), block = (32, 8)
// partial[ks][b][v] = sum_{k in chunk} h[b][k]*fcW[v][k]
#define PBM 32
#define PBK 16
__global__ __launch_bounds__(256, 1)
void pred_part(int pcur, const float* __restrict__ fcW)
{
    const float* __restrict__ h = g_h[pcur];
    __shared__ float As[PBK][PBM+4];
    __shared__ float Bs[PBK][VV+4];

    const int row0 = blockIdx.x * PBM;
    const int k0   = blockIdx.y * (HH/8);     // 128-wide K chunk
    const int tx = threadIdx.x, ty = threadIdx.y;
    const int tid = ty*32 + tx;

    float acc[4][4];
    #pragma unroll
    for (int i = 0; i < 4; i++)
        #pragma unroll
        for (int j = 0; j < 4; j++) acc[i][j] = 0.0f;

    for (int kt = 0; kt < HH/8; kt += PBK) {
        if (tid < 128) {                     // A: 32 rows x 16 k = 128 float4
            int ar = tid >> 2;
            int ak = (tid & 3) << 2;
            float4 av = *(const float4*)&h[(row0+ar)*HH + k0 + kt + ak];
            As[ak+0][ar] = av.x; As[ak+1][ar] = av.y;
            As[ak+2][ar] = av.z; As[ak+3][ar] = av.w;
        }
        #pragma unroll
        for (int l = 0; l < 2; l++) {        // B: 128 cols x 16 k = 512 float4
            int t2 = l*256 + tid;
            int bc = t2 >> 2;
            int bk = (t2 & 3) << 2;
            float4 bv = *(const float4*)&fcW[bc*HH + k0 + kt + bk];
            Bs[bk+0][bc] = bv.x; Bs[bk+1][bc] = bv.y;
            Bs[bk+2][bc] = bv.z; Bs[bk+3][bc] = bv.w;
        }
        __syncthreads();
        #pragma unroll
        for (int kk = 0; kk < PBK; kk++) {
            float4 a = *(const float4*)&As[kk][ty*4];
            float4 b = *(const float4*)&Bs[kk][tx*4];
            float av[4] = {a.x,a.y,a.z,a.w};
            float bv[4] = {b.x,b.y,b.z,b.w};
            #pragma unroll
            for (int i = 0; i < 4; i++)
                #pragma unroll
                for (int j = 0; j < 4; j++) acc[i][j] += av[i]*bv[j];
        }
        __syncthreads();
    }
    float* dst = g_pred_part[blockIdx.y];
    #pragma unroll
    for (int i = 0; i < 4; i++)
        #pragma unroll
        for (int j = 0; j < 4; j++)
            dst[(row0 + ty*4 + i)*VV + tx*4 + j] = acc[i][j];
}

// ---------------- reduce partials, add bias, write out, argmax -> next token ----
// grid = NB blocks, 128 threads (one per vocab entry)
__global__ void argmax_write(float* __restrict__ out,
                             const float* __restrict__ fcb,
                             const int* __restrict__ trg,
                             const void* __restrict__ tfr,
                             int t_out)
{
    int b = blockIdx.x;
    int v = threadIdx.x;
    float acc = fcb[v];
    #pragma unroll
    for (int p = 0; p < 8; p++) acc += g_pred_part[p][b*VV + v];
    out[b*(TT*VV) + t_out*VV + v] = acc;

    __shared__ float sval[128];
    __shared__ int   sidx[128];
    sval[v] = acc; sidx[v] = v;
    __syncthreads();
    for (int s = 64; s > 0; s >>= 1) {
        if (v < s) {
            // first-occurrence argmax (lowest index wins ties) like jnp.argmax
            if (sval[v+s] > sval[v] ||
                (sval[v+s] == sval[v] && sidx[v+s] < sidx[v])) {
                sval[v] = sval[v+s]; sidx[v] = sidx[v+s];
            }
        }
        __syncthreads();
    }
    if (v == 0) {
        int   ti  = ((const int*)tfr)[0];
        float tfv = ((const float*)tfr)[0];
        bool tf = (ti > 0) || (tfv > 0.0f);
        g_tok[b] = tf ? trg[b*TT + t_out] : sidx[0];
    }
}

// ---------------- host ----------------
extern "C" void kernel_launch(void* const* d_in, const int* in_sizes, int n_in,
                              void* d_out, int out_size)
{
    const int*   src     = (const int*)  d_in[0];
    const int*   trg     = (const int*)  d_in[1];
    const float* emb_src = (const float*)d_in[2];
    const float* emb_trg = (const float*)d_in[3];
    const float* enc_Wih = (const float*)d_in[4];
    const float* enc_Whh = (const float*)d_in[5];
    const float* enc_bih = (const float*)d_in[6];
    const float* enc_bhh = (const float*)d_in[7];
    const float* dec_Wih = (const float*)d_in[8];
    const float* dec_Whh = (const float*)d_in[9];
    const float* dec_bih = (const float*)d_in[10];
    const float* dec_bhh = (const float*)d_in[11];
    const float* fc_W    = (const float*)d_in[12];
    const float* fc_b    = (const float*)d_in[13];
    const void*  tfr     =               d_in[14];
    float* out = (float*)d_out;

    build_tables<<<(2*VV*G3)/256, 256>>>(emb_src, enc_Wih, enc_bih,
                                         emb_trg, dec_Wih, dec_bih);
    init_kernel<<<(NB*HH)/256, 256>>>(out, trg);

    dim3 gblk(32, 8);
    dim3 ggrid(HH/BN, NB/BM);   // (16, 8)
    int p = 0;

    // encoder: token for step t is src[b*S + t] (stride S); table_sel=0
    for (int t = 0; t < SS; t++) {
        gru_step<<<ggrid, gblk>>>(p, enc_Whh, enc_bhh, 0, src + t, SS);
        p ^= 1;
    }
    // decoder: tokens from g_tok (ext_tok = nullptr); table_sel=1
    dim3 pgrid(NB/PBM, 8);
    for (int t = 0; t < TT-1; t++) {
        gru_step<<<ggrid, gblk>>>(p, dec_Whh, dec_bhh, 1, (const int*)nullptr, 1);
        p ^= 1;
        pred_part<<<pgrid, gblk>>>(p, fc_W);
        argmax_write<<<NB, VV>>>(out, fc_b, trg, tfr, t + 1);
    }
}